// round 2
// baseline (speedup 1.0000x reference)
#include <cuda_runtime.h>
#include <cstdint>

#define BATCH   128
#define INPUTS  65536
#define OUTPUTS 65536
#define TOPK    32

// Scratch (allocation-free rule: __device__ globals)
__device__ float g_xT[(size_t)INPUTS * BATCH];     // 32 MB: x transposed [input, batch]
__device__ float g_tcT[(size_t)OUTPUTS * TOPK];    // 8 MB: top_c transposed [o, k]
__device__ int   g_idxT[(size_t)OUTPUTS * TOPK];   // 8 MB: indices transposed, int32
__device__ int   g_idx_is64;                       // dtype flag set by k_detect

// ---------------------------------------------------------------------------
// Kernel 0: detect whether top_indices is int64 or int32.
// Samples 256 int64-words from the first 8 MB (valid under both layouts).
// Genuine int64 indices are < 65536 (high word 0); fused int32 pairs are huge
// unless the high index is 0 (p = 2^-16 per sample).
// ---------------------------------------------------------------------------
__global__ void k_detect(const unsigned long long* __restrict__ p) {
    if (threadIdx.x == 0 && blockIdx.x == 0) {
        int is64 = 1;
        for (int i = 0; i < 256; i++) {
            if (p[(size_t)i * 4096] >= (unsigned long long)INPUTS) { is64 = 0; break; }
        }
        g_idx_is64 = is64;
    }
}

// ---------------------------------------------------------------------------
// Kernel 1: transpose x [BATCH, INPUTS] -> g_xT [INPUTS, BATCH]
// ---------------------------------------------------------------------------
__global__ __launch_bounds__(256) void k_transpose_x(const float* __restrict__ x) {
    __shared__ float tile[32][33];
    const int tx = threadIdx.x, ty = threadIdx.y;
    const int o_in = blockIdx.x * 32 + tx;      // column (input index)
    const int b0   = blockIdx.y * 32;           // row base (batch)
#pragma unroll
    for (int i = 0; i < 32; i += 8) {
        tile[ty + i][tx] = x[(size_t)(b0 + ty + i) * INPUTS + o_in];
    }
    __syncthreads();
#pragma unroll
    for (int i = 0; i < 32; i += 8) {
        const int o_out = blockIdx.x * 32 + ty + i;
        g_xT[(size_t)o_out * BATCH + b0 + tx] = tile[tx][ty + i];
    }
}

// ---------------------------------------------------------------------------
// Kernel 2: transpose top_c [TOPK, OUTPUTS] -> g_tcT [OUTPUTS, TOPK]
//           and top_indices -> g_idxT [OUTPUTS, TOPK] (int32), dtype-adaptive
// ---------------------------------------------------------------------------
__global__ __launch_bounds__(256) void k_prep(const float* __restrict__ tc,
                                              const void* __restrict__ idx_raw) {
    __shared__ float tct[32][33];
    __shared__ int   ixt[32][33];
    const int tx = threadIdx.x, ty = threadIdx.y;
    const int o_in = blockIdx.x * 32 + tx;
    const int is64 = g_idx_is64;
    const long long* __restrict__ idx64 = (const long long*)idx_raw;
    const int*       __restrict__ idx32 = (const int*)idx_raw;
#pragma unroll
    for (int i = 0; i < 32; i += 8) {
        const int k = ty + i;
        const size_t e = (size_t)k * OUTPUTS + o_in;
        tct[k][tx] = tc[e];
        ixt[k][tx] = (is64 ? (int)idx64[e] : idx32[e]) & (INPUTS - 1);
    }
    __syncthreads();
#pragma unroll
    for (int i = 0; i < 32; i += 8) {
        const int o_out = blockIdx.x * 32 + ty + i;
        g_tcT[(size_t)o_out * TOPK + tx]  = tct[tx][ty + i];
        g_idxT[(size_t)o_out * TOPK + tx] = ixt[tx][ty + i];
    }
}

// ---------------------------------------------------------------------------
// Kernel 3: main. One warp per output column o.
//   lane l holds (c_l, idx_l); warp-shuffle softmax over k;
//   32 iterations: broadcast (idx_k, w_k), gather float4 row slice of xT
//   (contiguous 512B per warp per k), FMA into per-lane float4 acc (4 batches).
//   Stage [8 o][128 b] tile in smem, write out with full-sector float4 stores.
// ---------------------------------------------------------------------------
__global__ __launch_bounds__(256) void k_main(float* __restrict__ out) {
    __shared__ float sm[8][BATCH];            // [o_local][b]
    const int warp = threadIdx.x >> 5;
    const int lane = threadIdx.x & 31;
    const int o    = blockIdx.x * 8 + warp;

    const float c  = g_tcT[(size_t)o * TOPK + lane];   // coalesced 128B per warp
    const int   ix = g_idxT[(size_t)o * TOPK + lane];  // coalesced 128B per warp

    // warp softmax over the 32 lanes (k dimension), C_SPARSITY = 1.0
    float m = c;
#pragma unroll
    for (int s = 16; s > 0; s >>= 1) m = fmaxf(m, __shfl_xor_sync(0xffffffffu, m, s));
    float e = __expf(c - m);
    float ssum = e;
#pragma unroll
    for (int s = 16; s > 0; s >>= 1) ssum += __shfl_xor_sync(0xffffffffu, ssum, s);
    const float w = e / ssum;

    const float4* __restrict__ xT4 = reinterpret_cast<const float4*>(g_xT);
    float4 acc = make_float4(0.f, 0.f, 0.f, 0.f);
#pragma unroll
    for (int k = 0; k < TOPK; k++) {
        const int   ik = __shfl_sync(0xffffffffu, ix, k);
        const float wk = __shfl_sync(0xffffffffu, w, k);
        const float4 g = xT4[(size_t)ik * (BATCH / 4) + lane];  // 512B contiguous/warp
        acc.x = fmaf(wk, g.x, acc.x);
        acc.y = fmaf(wk, g.y, acc.y);
        acc.z = fmaf(wk, g.z, acc.z);
        acc.w = fmaf(wk, g.w, acc.w);
    }

    // stage: lane l owns batches 4l..4l+3 of column o
    reinterpret_cast<float4*>(sm[warp])[lane] = acc;
    __syncthreads();

    // write out: thread t -> b = t/2, 4 consecutive o starting at (t&1)*4
    const int t  = threadIdx.x;
    const int b  = t >> 1;
    const int j  = (t & 1) * 4;
    const int o0 = blockIdx.x * 8;
    const float4 v = make_float4(sm[j + 0][b], sm[j + 1][b], sm[j + 2][b], sm[j + 3][b]);
    *reinterpret_cast<float4*>(&out[(size_t)b * OUTPUTS + o0 + j]) = v;
}

// ---------------------------------------------------------------------------
extern "C" void kernel_launch(void* const* d_in, const int* in_sizes, int n_in,
                              void* d_out, int out_size) {
    const float* x   = (const float*)d_in[0];      // [128, 65536] f32
    const float* tc  = (const float*)d_in[1];      // [32, 65536]  f32
    const void*  idx = d_in[2];                    // [32, 65536]  i64 OR i32 (detected)
    float* out = (float*)d_out;                    // [128, 65536] f32

    dim3 tb(32, 8);
    k_detect<<<1, 32>>>((const unsigned long long*)idx);
    k_transpose_x<<<dim3(INPUTS / 32, BATCH / 32), tb>>>(x);
    k_prep<<<dim3(OUTPUTS / 32, 1), tb>>>(tc, idx);
    k_main<<<OUTPUTS / 8, 256>>>(out);
}

// round 3
// speedup vs baseline: 1.2000x; 1.2000x over previous
#include <cuda_runtime.h>
#include <cuda_fp16.h>
#include <cstdint>

#define BATCH   128
#define INPUTS  65536
#define OUTPUTS 65536
#define TOPK    32

// Scratch (allocation-free rule: __device__ globals)
__device__ __half g_xTh[(size_t)INPUTS * BATCH];   // 16 MB: x transposed [input, batch], fp16
__device__ float  g_tcT[(size_t)OUTPUTS * TOPK];   // 8 MB: top_c transposed [o, k]
__device__ int    g_idxT[(size_t)OUTPUTS * TOPK];  // 8 MB: indices transposed, int32
__device__ int    g_idx_is64;                      // dtype flag set by k_detect

// ---------------------------------------------------------------------------
// Kernel 0: detect whether top_indices is int64 or int32 (parallel, 1 block).
// Samples 256 int64-words from the first 8 MB (safe under both layouts).
// Genuine int64 indices are < 65536 (high word 0); fused int32 pairs are huge
// unless the second index is 0 (p = 2^-16 per sample).
// ---------------------------------------------------------------------------
__global__ void k_detect(const unsigned long long* __restrict__ p) {
    const int i = threadIdx.x;                      // 256 threads
    const int big = (p[(size_t)i * 4096] >= (unsigned long long)INPUTS) ? 1 : 0;
    const int any = __syncthreads_or(big);
    if (i == 0) g_idx_is64 = !any;
}

// ---------------------------------------------------------------------------
// Kernel 1: transpose x [BATCH, INPUTS] -> g_xTh [INPUTS, BATCH] (fp16)
// Half stores: 32 lanes x 2B contiguous = 64B = 2 full sectors, no waste.
// ---------------------------------------------------------------------------
__global__ __launch_bounds__(256) void k_transpose_x(const float* __restrict__ x) {
    __shared__ float tile[32][33];
    const int tx = threadIdx.x, ty = threadIdx.y;
    const int o_in = blockIdx.x * 32 + tx;      // column (input index)
    const int b0   = blockIdx.y * 32;           // row base (batch)
#pragma unroll
    for (int i = 0; i < 32; i += 8) {
        tile[ty + i][tx] = x[(size_t)(b0 + ty + i) * INPUTS + o_in];
    }
    __syncthreads();
#pragma unroll
    for (int i = 0; i < 32; i += 8) {
        const int o_out = blockIdx.x * 32 + ty + i;
        g_xTh[(size_t)o_out * BATCH + b0 + tx] = __float2half_rn(tile[tx][ty + i]);
    }
}

// ---------------------------------------------------------------------------
// Kernel 2: transpose top_c [TOPK, OUTPUTS] -> g_tcT [OUTPUTS, TOPK]
//           and top_indices -> g_idxT [OUTPUTS, TOPK] (int32), dtype-adaptive
// ---------------------------------------------------------------------------
__global__ __launch_bounds__(256) void k_prep(const float* __restrict__ tc,
                                              const void* __restrict__ idx_raw) {
    __shared__ float tct[32][33];
    __shared__ int   ixt[32][33];
    const int tx = threadIdx.x, ty = threadIdx.y;
    const int o_in = blockIdx.x * 32 + tx;
    const int is64 = g_idx_is64;
    const long long* __restrict__ idx64 = (const long long*)idx_raw;
    const int*       __restrict__ idx32 = (const int*)idx_raw;
#pragma unroll
    for (int i = 0; i < 32; i += 8) {
        const int k = ty + i;
        const size_t e = (size_t)k * OUTPUTS + o_in;
        tct[k][tx] = tc[e];
        ixt[k][tx] = (is64 ? (int)idx64[e] : idx32[e]) & (INPUTS - 1);
    }
    __syncthreads();
#pragma unroll
    for (int i = 0; i < 32; i += 8) {
        const int o_out = blockIdx.x * 32 + ty + i;
        g_tcT[(size_t)o_out * TOPK + tx]  = tct[tx][ty + i];
        g_idxT[(size_t)o_out * TOPK + tx] = ixt[tx][ty + i];
    }
}

// ---------------------------------------------------------------------------
// Kernel 3: main. One warp per output column o.
//   lane l holds (c_l, idx_l); warp-shuffle softmax over k;
//   32 iterations: broadcast (idx_k, w_k), gather 8B (4 fp16) row slice of xTh
//   (256B contiguous per warp per k = 2 L1 wavefronts), fp32 FMA accumulate.
//   Stage [8 o][128 b] tile in smem, write out with full-sector float4 stores.
// ---------------------------------------------------------------------------
__global__ __launch_bounds__(256) void k_main(float* __restrict__ out) {
    __shared__ float sm[8][BATCH];            // [o_local][b]
    const int warp = threadIdx.x >> 5;
    const int lane = threadIdx.x & 31;
    const int o    = blockIdx.x * 8 + warp;

    const float c  = g_tcT[(size_t)o * TOPK + lane];   // coalesced 128B per warp
    const int   ix = g_idxT[(size_t)o * TOPK + lane];  // coalesced 128B per warp

    // warp softmax over the 32 lanes (k dimension), C_SPARSITY = 1.0
    float m = c;
#pragma unroll
    for (int s = 16; s > 0; s >>= 1) m = fmaxf(m, __shfl_xor_sync(0xffffffffu, m, s));
    float e = __expf(c - m);
    float ssum = e;
#pragma unroll
    for (int s = 16; s > 0; s >>= 1) ssum += __shfl_xor_sync(0xffffffffu, ssum, s);
    const float w = e / ssum;

    const uint2* __restrict__ xT2 = reinterpret_cast<const uint2*>(g_xTh);
    float4 acc = make_float4(0.f, 0.f, 0.f, 0.f);
#pragma unroll
    for (int k = 0; k < TOPK; k++) {
        const int   ik = __shfl_sync(0xffffffffu, ix, k);
        const float wk = __shfl_sync(0xffffffffu, w, k);
        uint2 raw = xT2[(size_t)ik * (BATCH / 4) + lane];   // 256B contiguous/warp
        const __half2 h01 = *reinterpret_cast<const __half2*>(&raw.x);
        const __half2 h23 = *reinterpret_cast<const __half2*>(&raw.y);
        const float2 f01 = __half22float2(h01);
        const float2 f23 = __half22float2(h23);
        acc.x = fmaf(wk, f01.x, acc.x);
        acc.y = fmaf(wk, f01.y, acc.y);
        acc.z = fmaf(wk, f23.x, acc.z);
        acc.w = fmaf(wk, f23.y, acc.w);
    }

    // stage: lane l owns batches 4l..4l+3 of column o
    reinterpret_cast<float4*>(sm[warp])[lane] = acc;
    __syncthreads();

    // write out: thread t -> b = t/2, 4 consecutive o starting at (t&1)*4
    const int t  = threadIdx.x;
    const int b  = t >> 1;
    const int j  = (t & 1) * 4;
    const int o0 = blockIdx.x * 8;
    const float4 v = make_float4(sm[j + 0][b], sm[j + 1][b], sm[j + 2][b], sm[j + 3][b]);
    *reinterpret_cast<float4*>(&out[(size_t)b * OUTPUTS + o0 + j]) = v;
}

// ---------------------------------------------------------------------------
extern "C" void kernel_launch(void* const* d_in, const int* in_sizes, int n_in,
                              void* d_out, int out_size) {
    const float* x   = (const float*)d_in[0];      // [128, 65536] f32
    const float* tc  = (const float*)d_in[1];      // [32, 65536]  f32
    const void*  idx = d_in[2];                    // [32, 65536]  i64 OR i32 (detected)
    float* out = (float*)d_out;                    // [128, 65536] f32

    dim3 tb(32, 8);
    k_detect<<<1, 256>>>((const unsigned long long*)idx);
    k_transpose_x<<<dim3(INPUTS / 32, BATCH / 32), tb>>>(x);
    k_prep<<<dim3(OUTPUTS / 32, 1), tb>>>(tc, idx);
    k_main<<<OUTPUTS / 8, 256>>>(out);
}